// round 1
// baseline (speedup 1.0000x reference)
#include <cuda_runtime.h>

// Correlation layer: out[b, di*21+dj, h, w] = (1/64) * sum_c f1[b,c,h,w] * f2pad[b,c,h+di,w+dj]
// B=4, C=64, H=W=128, MAX_DISP=10, KS=21 (441 displacements), fp32.

#define B_      4
#define C_      64
#define H_      128
#define W_      128
#define KS_     21
#define PAD_    10

#define HB   4      // h rows per CTA
#define DIB  3      // di values per CTA
#define CC   16     // channels per smem chunk
#define PW   152    // padded f2 row width (covers x in [0,148))
#define NROW (HB + DIB - 1)  // 6 f2 rows per CTA

// float strides padded so that consecutive row-blocks differ by 16B mod 128B
// (conflict-free 4-phase LDS.128 across the hl lane dimension)
#define F1_STRIDE (CC * W_ + 4)   // 2052 floats per h-row block
#define F2_STRIDE (CC * PW + 4)   // 2436 floats per f2-row block
#define SMEM_F1   (HB * F1_STRIDE)     // 8208 floats
#define SMEM_F2   (NROW * F2_STRIDE)   // 14616 floats
#define SMEM_BYTES ((SMEM_F1 + SMEM_F2) * 4)  // 91296 B

#define NTHREADS 288   // 9 warps = 3 djg * 3 dil; lanes = 8 wg * 4 hl

// Per-chunk inner compute. DJG in {0,1,2}; thread covers dj = DJG + 3k, k=0..6,
// and w in [w0, w0+16). f2 staged shifted so loads are aligned LDS.128; the
// 36-float window [w0, w0+36) covers all needed f2 values with static indices.
template <int DJG>
__device__ __forceinline__ void compute_chunk(const float* __restrict__ f1p,
                                              const float* __restrict__ f2p,
                                              float (&acc)[7][16]) {
#pragma unroll
    for (int c = 0; c < CC; c++) {
        const float4* f1v = reinterpret_cast<const float4*>(f1p + c * W_);
        const float4* f2v = reinterpret_cast<const float4*>(f2p + c * PW);
        float fa[16];
        float fb[36];
#pragma unroll
        for (int i = 0; i < 4; i++) {
            float4 t = f1v[i];
            fa[4 * i + 0] = t.x; fa[4 * i + 1] = t.y;
            fa[4 * i + 2] = t.z; fa[4 * i + 3] = t.w;
        }
#pragma unroll
        for (int i = 0; i < 9; i++) {
            float4 t = f2v[i];
            fb[4 * i + 0] = t.x; fb[4 * i + 1] = t.y;
            fb[4 * i + 2] = t.z; fb[4 * i + 3] = t.w;
        }
#pragma unroll
        for (int k = 0; k < 7; k++) {
#pragma unroll
            for (int wi = 0; wi < 16; wi++) {
                acc[k][wi] = fmaf(fa[wi], fb[DJG + 3 * k + wi], acc[k][wi]);
            }
        }
    }
}

extern __shared__ float smem[];

__global__ __launch_bounds__(NTHREADS, 1)
void corr_kernel(const float* __restrict__ f1g,
                 const float* __restrict__ f2g,
                 float* __restrict__ out) {
    float* f1s = smem;
    float* f2s = smem + SMEM_F1;

    const int tid  = threadIdx.x;
    const int warp = tid >> 5;
    const int lane = tid & 31;
    const int djg  = warp % 3;      // dj phase (uniform per warp)
    const int dil  = warp / 3;      // local di (uniform per warp)
    const int wg   = lane & 7;
    const int hl   = lane >> 3;
    const int w0   = wg * 16;

    const int b   = blockIdx.z;
    const int h0  = blockIdx.y * HB;
    const int di0 = blockIdx.x * DIB;
    const int r0  = h0 + di0 - PAD_;   // first f2 source row (may be OOB -> zeros)

    float acc[7][16];
#pragma unroll
    for (int k = 0; k < 7; k++)
#pragma unroll
        for (int wi = 0; wi < 16; wi++) acc[k][wi] = 0.f;

    const float* f1p = f1s + hl * F1_STRIDE + w0;
    const float* f2p = f2s + (hl + dil) * F2_STRIDE + w0;

    for (int cc = 0; cc < C_ / CC; cc++) {
        const int cb = cc * CC;
        __syncthreads();

        // ---- stage f1 chunk: HB x CC x 128 floats as float4 ----
        for (int idx = tid; idx < HB * CC * (W_ / 4); idx += NTHREADS) {
            int w4 = idx & 31;          // W_/4 = 32
            int c  = (idx >> 5) & 15;   // CC = 16
            int h  = idx >> 9;
            float4 v = *reinterpret_cast<const float4*>(
                f1g + ((size_t)(b * C_ + cb + c) * H_ + (h0 + h)) * W_ + w4 * 4);
            *reinterpret_cast<float4*>(f1s + h * F1_STRIDE + c * W_ + w4 * 4) = v;
        }

        // ---- stage f2 chunk: NROW x CC x PW floats, shifted by PAD_, zero-padded ----
        for (int idx = tid; idx < NROW * CC * PW; idx += NTHREADS) {
            int x  = idx % PW;
            int t2 = idx / PW;
            int c  = t2 & 15;
            int r  = t2 >> 4;
            int h2 = r0 + r;
            int xw = x - PAD_;
            float v = 0.f;
            if (h2 >= 0 && h2 < H_ && xw >= 0 && xw < W_)
                v = f2g[((size_t)(b * C_ + cb + c) * H_ + h2) * W_ + xw];
            f2s[r * F2_STRIDE + c * PW + x] = v;
        }

        __syncthreads();

        // djg is uniform per warp: no divergence, static f2 indexing per branch.
        if (djg == 0)      compute_chunk<0>(f1p, f2p, acc);
        else if (djg == 1) compute_chunk<1>(f1p, f2p, acc);
        else               compute_chunk<2>(f1p, f2p, acc);
    }

    // ---- epilogue: 7 dj rows of 16 contiguous floats each ----
    const float inv = 1.0f / 64.0f;
    const int di = di0 + dil;
    const int h  = h0 + hl;
#pragma unroll
    for (int k = 0; k < 7; k++) {
        const int d = di * KS_ + djg + 3 * k;
        float* o = out + (((size_t)b * (KS_ * KS_) + d) * H_ + h) * W_ + w0;
#pragma unroll
        for (int i = 0; i < 4; i++) {
            float4 v = make_float4(acc[k][4 * i + 0] * inv,
                                   acc[k][4 * i + 1] * inv,
                                   acc[k][4 * i + 2] * inv,
                                   acc[k][4 * i + 3] * inv);
            *reinterpret_cast<float4*>(o + 4 * i) = v;
        }
    }
}

extern "C" void kernel_launch(void* const* d_in, const int* in_sizes, int n_in,
                              void* d_out, int out_size) {
    const float* f1 = (const float*)d_in[0];
    const float* f2 = (const float*)d_in[1];
    float* out = (float*)d_out;

    // 91.3 KB dynamic smem needs the opt-in attribute (idempotent, host-side,
    // safe under graph capture).
    cudaFuncSetAttribute(corr_kernel, cudaFuncAttributeMaxDynamicSharedMemorySize,
                         SMEM_BYTES);

    dim3 grid(KS_ / DIB, H_ / HB, B_);   // (7, 32, 4) = 896 CTAs
    corr_kernel<<<grid, NTHREADS, SMEM_BYTES>>>(f1, f2, out);
}

// round 2
// speedup vs baseline: 1.5737x; 1.5737x over previous
#include <cuda_runtime.h>

// Correlation layer: out[b, di*21+dj, h, w] = (1/64) * sum_c f1[b,c,h,w] * f2pad[b,c,h+di,w+dj]
// B=4, C=64, H=W=128, MAX_DISP=10, KS=21 (441 displacements), fp32.

#define B_      4
#define C_      64
#define H_      128
#define W_      128
#define KS_     21
#define PAD_    10

#define HB   4      // h rows per CTA
#define DIB  3      // di values per CTA
#define CC   16     // channels per smem chunk
#define PW   152    // padded f2 row width (covers x in [0,148))
#define NROW (HB + DIB - 1)  // 6 f2 rows per CTA

// float strides padded so that consecutive row-blocks differ by 16B mod 128B
#define F1_STRIDE (CC * W_ + 4)   // 2052 floats (8208 B ≡ 16 mod 128)
#define F2_STRIDE (CC * PW + 4)   // 2436 floats (9744 B ≡ 16 mod 128)
#define SMEM_F1   (HB * F1_STRIDE)     // 8208 floats
#define SMEM_F2   (NROW * F2_STRIDE)   // 14616 floats
#define SMEM_BYTES ((SMEM_F1 + SMEM_F2) * 4)  // 91296 B

#define NTHREADS 288   // 9 warps = 3 djg * 3 dil

// Per-chunk inner compute. DJG in {0,1,2}; thread covers dj = DJG + 3k, k=0..6,
// and w in [w0, w0+16). f2 staged shifted so loads are aligned LDS.128; the
// 36-float window [w0, w0+36) covers all needed f2 values with static indices.
template <int DJG>
__device__ __forceinline__ void compute_chunk(const float* __restrict__ f1p,
                                              const float* __restrict__ f2p,
                                              float (&acc)[7][16]) {
#pragma unroll
    for (int c = 0; c < CC; c++) {
        const float4* f1v = reinterpret_cast<const float4*>(f1p + c * W_);
        const float4* f2v = reinterpret_cast<const float4*>(f2p + c * PW);
        float fa[16];
        float fb[36];
#pragma unroll
        for (int i = 0; i < 4; i++) {
            float4 t = f1v[i];
            fa[4 * i + 0] = t.x; fa[4 * i + 1] = t.y;
            fa[4 * i + 2] = t.z; fa[4 * i + 3] = t.w;
        }
#pragma unroll
        for (int i = 0; i < 9; i++) {
            float4 t = f2v[i];
            fb[4 * i + 0] = t.x; fb[4 * i + 1] = t.y;
            fb[4 * i + 2] = t.z; fb[4 * i + 3] = t.w;
        }
#pragma unroll
        for (int k = 0; k < 7; k++) {
#pragma unroll
            for (int wi = 0; wi < 16; wi++) {
                acc[k][wi] = fmaf(fa[wi], fb[DJG + 3 * k + wi], acc[k][wi]);
            }
        }
    }
}

extern __shared__ float smem[];

__global__ __launch_bounds__(NTHREADS, 1)
void corr_kernel(const float* __restrict__ f1g,
                 const float* __restrict__ f2g,
                 float* __restrict__ out) {
    float* f1s = smem;
    float* f2s = smem + SMEM_F1;

    const int tid  = threadIdx.x;
    const int warp = tid >> 5;
    const int lane = tid & 31;
    const int djg  = warp % 3;      // dj phase (uniform per warp)
    const int dil  = warp / 3;      // local di (uniform per warp)

    // Conflict-free lane map: within every quarter-warp (LDS.128 phase group),
    // the 8 lanes are (wb in {0,1}) x (hl in {0..3}) -> address offsets
    // wb*64 + hl*16 mod 128 cover all eight 16B segments. wg = 2*qw + wb keeps
    // each thread's 16-float w-tile contiguous (qw*128 B is 0 mod 128).
    const int qw   = lane >> 3;
    const int hl   = (lane >> 1) & 3;
    const int wb   = lane & 1;
    const int wg   = 2 * qw + wb;
    const int w0   = wg * 16;

    const int b   = blockIdx.z;
    const int h0  = blockIdx.y * HB;
    const int di0 = blockIdx.x * DIB;
    const int r0  = h0 + di0 - PAD_;   // first f2 source row (may be OOB -> zeros)

    float acc[7][16];
#pragma unroll
    for (int k = 0; k < 7; k++)
#pragma unroll
        for (int wi = 0; wi < 16; wi++) acc[k][wi] = 0.f;

    const float* f1p = f1s + hl * F1_STRIDE + w0;
    const float* f2p = f2s + (hl + dil) * F2_STRIDE + w0;

    for (int cc = 0; cc < C_ / CC; cc++) {
        const int cb = cc * CC;
        __syncthreads();

        // ---- stage f1 chunk: HB x CC x 128 floats as float4 ----
        for (int idx = tid; idx < HB * CC * (W_ / 4); idx += NTHREADS) {
            int w4 = idx & 31;          // W_/4 = 32
            int c  = (idx >> 5) & 15;   // CC = 16
            int h  = idx >> 9;
            float4 v = *reinterpret_cast<const float4*>(
                f1g + ((size_t)(b * C_ + cb + c) * H_ + (h0 + h)) * W_ + w4 * 4);
            *reinterpret_cast<float4*>(f1s + h * F1_STRIDE + c * W_ + w4 * 4) = v;
        }

        // ---- stage f2 chunk: NROW x CC x PW floats, shifted by PAD_, zero-padded ----
        for (int idx = tid; idx < NROW * CC * PW; idx += NTHREADS) {
            int x  = idx % PW;
            int t2 = idx / PW;
            int c  = t2 & 15;
            int r  = t2 >> 4;
            int h2 = r0 + r;
            int xw = x - PAD_;
            float v = 0.f;
            if (h2 >= 0 && h2 < H_ && xw >= 0 && xw < W_)
                v = f2g[((size_t)(b * C_ + cb + c) * H_ + h2) * W_ + xw];
            f2s[r * F2_STRIDE + c * PW + x] = v;
        }

        __syncthreads();

        // djg is uniform per warp: no divergence, static f2 indexing per branch.
        if (djg == 0)      compute_chunk<0>(f1p, f2p, acc);
        else if (djg == 1) compute_chunk<1>(f1p, f2p, acc);
        else               compute_chunk<2>(f1p, f2p, acc);
    }

    // ---- epilogue: 7 dj rows of 16 contiguous floats each ----
    const float inv = 1.0f / 64.0f;
    const int di = di0 + dil;
    const int h  = h0 + hl;
#pragma unroll
    for (int k = 0; k < 7; k++) {
        const int d = di * KS_ + djg + 3 * k;
        float* o = out + (((size_t)b * (KS_ * KS_) + d) * H_ + h) * W_ + w0;
#pragma unroll
        for (int i = 0; i < 4; i++) {
            float4 v = make_float4(acc[k][4 * i + 0] * inv,
                                   acc[k][4 * i + 1] * inv,
                                   acc[k][4 * i + 2] * inv,
                                   acc[k][4 * i + 3] * inv);
            *reinterpret_cast<float4*>(o + 4 * i) = v;
        }
    }
}

extern "C" void kernel_launch(void* const* d_in, const int* in_sizes, int n_in,
                              void* d_out, int out_size) {
    const float* f1 = (const float*)d_in[0];
    const float* f2 = (const float*)d_in[1];
    float* out = (float*)d_out;

    cudaFuncSetAttribute(corr_kernel, cudaFuncAttributeMaxDynamicSharedMemorySize,
                         SMEM_BYTES);

    dim3 grid(KS_ / DIB, H_ / HB, B_);   // (7, 32, 4) = 896 CTAs
    corr_kernel<<<grid, NTHREADS, SMEM_BYTES>>>(f1, f2, out);
}

// round 3
// speedup vs baseline: 2.2831x; 1.4508x over previous
#include <cuda_runtime.h>
#include <cstdint>

// Correlation layer: out[b, di*21+dj, h, w] = (1/64) * sum_c f1[b,c,h,w] * f2pad[b,c,h+di,w+dj]
// B=4, C=64, H=W=128, MAX_DISP=10, KS=21 (441 displacements), fp32.

#define B_      4
#define C_      64
#define H_      128
#define W_      128
#define KS_     21
#define PAD_    10

#define HB   4      // h rows per CTA
#define DIB  3      // di values per CTA
#define CC   8      // channels per chunk (pow2 -> shift/mask staging indexing)
#define NCHUNK (C_ / CC)   // 8
#define PW   152    // padded f2 row width
#define NROW (HB + DIB - 1)  // 6 f2 rows per CTA

// strides padded so consecutive row-blocks differ by 16B mod 128B (conflict-free LDS.128)
#define F1_STRIDE (CC * W_ + 4)   // 1028 floats (4112 B ≡ 16 mod 128)
#define F2_STRIDE (CC * PW + 4)   // 1220 floats (4880 B ≡ 16 mod 128)
#define SMEM_F1   (HB * F1_STRIDE)     // 4112 floats
#define SMEM_F2   (NROW * F2_STRIDE)   // 7320 floats
#define BUF_FLOATS (SMEM_F1 + SMEM_F2) // 11432 floats per buffer
#define SMEM_BYTES (2 * BUF_FLOATS * 4)  // 91456 B (double buffered)

#define NTHREADS 288   // 9 warps = 3 djg * 3 dil

// ---------------- cp.async helpers ----------------
__device__ __forceinline__ void cp_async16(float* smem_dst, const float* gsrc) {
    uint32_t s = (uint32_t)__cvta_generic_to_shared(smem_dst);
    asm volatile("cp.async.cg.shared.global [%0], [%1], 16;\n" :: "r"(s), "l"(gsrc));
}
__device__ __forceinline__ void cp_async8(float* smem_dst, const float* gsrc) {
    uint32_t s = (uint32_t)__cvta_generic_to_shared(smem_dst);
    asm volatile("cp.async.ca.shared.global [%0], [%1], 8;\n" :: "r"(s), "l"(gsrc));
}
__device__ __forceinline__ void cp_commit() {
    asm volatile("cp.async.commit_group;\n" ::: "memory");
}
template <int N>
__device__ __forceinline__ void cp_wait() {
    asm volatile("cp.async.wait_group %0;\n" :: "n"(N) : "memory");
}

// ---------------- inner compute ----------------
// DJG in {0,1,2}; thread covers dj = DJG + 3k (k=0..6), w in [w0, w0+16).
template <int DJG>
__device__ __forceinline__ void compute_chunk(const float* __restrict__ f1p,
                                              const float* __restrict__ f2p,
                                              float (&acc)[7][16]) {
#pragma unroll
    for (int c = 0; c < CC; c++) {
        const float4* f1v = reinterpret_cast<const float4*>(f1p + c * W_);
        const float4* f2v = reinterpret_cast<const float4*>(f2p + c * PW);
        float fa[16];
        float fb[36];
#pragma unroll
        for (int i = 0; i < 4; i++) {
            float4 t = f1v[i];
            fa[4 * i + 0] = t.x; fa[4 * i + 1] = t.y;
            fa[4 * i + 2] = t.z; fa[4 * i + 3] = t.w;
        }
#pragma unroll
        for (int i = 0; i < 9; i++) {
            float4 t = f2v[i];
            fb[4 * i + 0] = t.x; fb[4 * i + 1] = t.y;
            fb[4 * i + 2] = t.z; fb[4 * i + 3] = t.w;
        }
#pragma unroll
        for (int k = 0; k < 7; k++) {
#pragma unroll
            for (int wi = 0; wi < 16; wi++) {
                acc[k][wi] = fmaf(fa[wi], fb[DJG + 3 * k + wi], acc[k][wi]);
            }
        }
    }
}

// ---------------- staging (cp.async) ----------------
// f1: HB x CC x 128 floats as float4; f2 valid interior rows as float2 into the
// pre-zeroed shifted layout (smem x = gmem xw + PAD_).
__device__ __forceinline__ void stage_chunk(const float* __restrict__ f1g,
                                            const float* __restrict__ f2g,
                                            float* f1b, float* f2b,
                                            int b, int cb, int h0, int r0,
                                            int rlo, int n2, int tid) {
    for (int i = tid; i < HB * CC * (W_ / 4); i += NTHREADS) {   // 1024 iters total
        int w4 = i & 31;
        int c  = (i >> 5) & (CC - 1);
        int h  = i >> 8;
        const float* src = f1g + ((size_t)(b * C_ + cb + c) * H_ + (h0 + h)) * W_ + w4 * 4;
        cp_async16(f1b + h * F1_STRIDE + c * W_ + w4 * 4, src);
    }
    for (int i = tid; i < n2; i += NTHREADS) {                   // up to 3072 iters
        int x2 = i & 63;
        int c  = (i >> 6) & (CC - 1);
        int r  = rlo + (i >> 9);
        const float* src = f2g + ((size_t)(b * C_ + cb + c) * H_ + (r0 + r)) * W_ + x2 * 2;
        cp_async8(f2b + r * F2_STRIDE + c * PW + PAD_ + x2 * 2, src);
    }
}

extern __shared__ float smem[];

__global__ __launch_bounds__(NTHREADS, 1)
void corr_kernel(const float* __restrict__ f1g,
                 const float* __restrict__ f2g,
                 float* __restrict__ out) {
    const int tid  = threadIdx.x;
    const int warp = tid >> 5;
    const int lane = tid & 31;
    const int djg  = warp % 3;      // dj phase (uniform per warp)
    const int dil  = warp / 3;      // local di (uniform per warp)

    // Conflict-free lane map: per quarter-warp, (wb,hl) -> wb*64 + hl*16 mod 128
    // covers all eight 16B segments.
    const int qw = lane >> 3;
    const int hl = (lane >> 1) & 3;
    const int wb = lane & 1;
    const int wg = 2 * qw + wb;
    const int w0 = wg * 16;

    const int b   = blockIdx.z;
    const int h0  = blockIdx.y * HB;
    const int di0 = blockIdx.x * DIB;
    const int r0  = h0 + di0 - PAD_;   // first f2 source row (may be OOB)

    // valid f2 row range [rlo, rhi) with 0 <= r0+r < H_
    int rlo = (r0 < 0) ? -r0 : 0;
    int rhi = (r0 + NROW > H_) ? (H_ - r0) : NROW;
    if (rhi < rlo) { rlo = 0; rhi = 0; }
    if (rlo > NROW) { rlo = 0; rhi = 0; }
    const int n2 = (rhi - rlo) * (CC * 64);   // float2 count for valid interior

    float* buf0 = smem;
    float* buf1 = smem + BUF_FLOATS;

    // ---- one-time zero of both f2 regions (covers padding + OOB rows forever) ----
    {
        float4 z = make_float4(0.f, 0.f, 0.f, 0.f);
        float4* z0 = reinterpret_cast<float4*>(buf0 + SMEM_F1);
        float4* z1 = reinterpret_cast<float4*>(buf1 + SMEM_F1);
        for (int i = tid; i < SMEM_F2 / 4; i += NTHREADS) { z0[i] = z; z1[i] = z; }
    }
    __syncthreads();

    // ---- prologue: stage chunks 0 and 1 ----
    stage_chunk(f1g, f2g, buf0, buf0 + SMEM_F1, b, 0 * CC, h0, r0, rlo, n2, tid);
    cp_commit();
    stage_chunk(f1g, f2g, buf1, buf1 + SMEM_F1, b, 1 * CC, h0, r0, rlo, n2, tid);
    cp_commit();

    float acc[7][16];
#pragma unroll
    for (int k = 0; k < 7; k++)
#pragma unroll
        for (int wi = 0; wi < 16; wi++) acc[k][wi] = 0.f;

    const int f1off = hl * F1_STRIDE + w0;
    const int f2off = SMEM_F1 + (hl + dil) * F2_STRIDE + w0;

    for (int cc = 0; cc < NCHUNK; cc++) {
        float* buf = (cc & 1) ? buf1 : buf0;
        if (cc < NCHUNK - 1) cp_wait<1>(); else cp_wait<0>();
        __syncthreads();   // chunk cc data visible to all

        const float* f1p = buf + f1off;
        const float* f2p = buf + f2off;
        if (djg == 0)      compute_chunk<0>(f1p, f2p, acc);
        else if (djg == 1) compute_chunk<1>(f1p, f2p, acc);
        else               compute_chunk<2>(f1p, f2p, acc);

        __syncthreads();   // all readers done with buf before restaging it
        if (cc + 2 < NCHUNK)
            stage_chunk(f1g, f2g, buf, buf + SMEM_F1, b, (cc + 2) * CC, h0, r0,
                        rlo, n2, tid);
        cp_commit();       // empty groups complete immediately; keeps counting uniform
    }

    // ---- epilogue: 7 dj rows of 16 contiguous floats each ----
    const float inv = 1.0f / 64.0f;
    const int di = di0 + dil;
    const int h  = h0 + hl;
#pragma unroll
    for (int k = 0; k < 7; k++) {
        const int d = di * KS_ + djg + 3 * k;
        float* o = out + (((size_t)b * (KS_ * KS_) + d) * H_ + h) * W_ + w0;
#pragma unroll
        for (int i = 0; i < 4; i++) {
            float4 v = make_float4(acc[k][4 * i + 0] * inv,
                                   acc[k][4 * i + 1] * inv,
                                   acc[k][4 * i + 2] * inv,
                                   acc[k][4 * i + 3] * inv);
            *reinterpret_cast<float4*>(o + 4 * i) = v;
        }
    }
}

extern "C" void kernel_launch(void* const* d_in, const int* in_sizes, int n_in,
                              void* d_out, int out_size) {
    const float* f1 = (const float*)d_in[0];
    const float* f2 = (const float*)d_in[1];
    float* out = (float*)d_out;

    cudaFuncSetAttribute(corr_kernel, cudaFuncAttributeMaxDynamicSharedMemorySize,
                         SMEM_BYTES);

    dim3 grid(KS_ / DIB, H_ / HB, B_);   // (7, 32, 4) = 896 CTAs
    corr_kernel<<<grid, NTHREADS, SMEM_BYTES>>>(f1, f2, out);
}